// round 6
// baseline (speedup 1.0000x reference)
#include <cuda_runtime.h>
#include <math.h>

#define LSEQ 32
#define HID  8
#define BMAX 16384
#define RB   64

typedef unsigned long long ull;

// ---------------- scratch (static device arrays; no allocations) ----------------
__device__ float g_xv[2 * LSEQ * BMAX];   // [j][comp][B], comp0 = fa_vals, comp1 = X
__device__ float g_m [2 * LSEQ * BMAX];   // spline slopes, same layout
__device__ float g_z [HID * BMAX];        // final ODE state, [h][B]

// ---------------- math helpers ----------------
__device__ __forceinline__ float fast_tanh(float x) {
    float ax = fabsf(x);
    float e  = __expf(-2.0f * ax);
    float t  = __fdividef(1.0f - e, 1.0f + e);
    return (x < 0.0f) ? -t : t;
}
__device__ __forceinline__ float gelu_exact(float x) {
    return 0.5f * x * (1.0f + erff(x * 0.70710678118654752440f));
}
// packed dual-fp32 FMA: d.lo += a.lo*b.lo, d.hi += a.hi*b.hi  (identical arithmetic)
__device__ __forceinline__ void ffma2(ull &d, ull a, ull b) {
    asm("fma.rn.f32x2 %0, %1, %2, %0;" : "+l"(d) : "l"(a), "l"(b));
}
__device__ __forceinline__ ull splat2(float x) {
    ull r; asm("mov.b64 %0, {%1, %1};" : "=l"(r) : "f"(x)); return r;
}
__device__ __forceinline__ ull pack2(float lo, float hi) {
    ull r; asm("mov.b64 %0, {%1, %2};" : "=l"(r) : "f"(lo), "f"(hi)); return r;
}
__device__ __forceinline__ void unpack2(ull v, float &lo, float &hi) {
    asm("mov.b64 {%0, %1}, %2;" : "=f"(lo), "=f"(hi) : "l"(v));
}

// ---------------- kernel 1: per-row preprocessing ----------------
// push_zeros == shift right by pad = L - fl (valid entries occupy [0, fl)).
__global__ void setup_kernel(const float* __restrict__ Xin,
                             const float* __restrict__ Vin,
                             const int*   __restrict__ fa_len, int B)
{
    int b = blockIdx.x * blockDim.x + threadIdx.x;
    if (b >= B) return;
    const float* Xr = Xin + b * LSEQ;
    const float* Vr = Vin + b * LSEQ;
    int fl = fa_len[b];                       // in [16, 32]
    float sum = 0.0f;
    #pragma unroll
    for (int j = 0; j < LSEQ; j++) sum += Xr[j];
    float mean  = sum / (float)fl;
    float lastV = Vr[fl - 1];                 // from ORIGINAL fa_vals
    float lastX = (fl >= 17) ? (Xr[2 * fl - 33] / mean) : 0.0f;
    int pad = LSEQ - fl;

    float fv[LSEQ], fx[LSEQ];
    #pragma unroll
    for (int j = 0; j < LSEQ; j++) {
        int idx = j - pad;
        if (idx >= 0) { fv[j] = Vr[idx]; fx[j] = Xr[idx] / mean; }
        else          { fv[j] = lastV;   fx[j] = lastX; }
    }
    #pragma unroll
    for (int j = 0; j < LSEQ; j++) {
        float mv, mx;
        if (j == 0) { mv = fv[1] - fv[0];     mx = fx[1] - fx[0]; }
        else        { mv = fv[j] - fv[j - 1]; mx = fx[j] - fx[j - 1]; }
        g_xv[(2 * j + 0) * B + b] = fv[j];
        g_xv[(2 * j + 1) * B + b] = fx[j];
        g_m [(2 * j + 0) * B + b] = mv;
        g_m [(2 * j + 1) * B + b] = mx;
    }
}

// ---------------- ODE core ----------------
// f(z) = tanh(W2 * relu(W1 z + b1) + b2) reshaped (8,2); F = f . dX
// Layer-1 packed over hidden-unit pairs: sW1p[jp] holds 8 ull = (W1[2jp,k], W1[2jp+1,k])
// Layer-2 packed over output pairs:      sW2p[j]  holds 8 ull = (W2t[j, 2i], W2t[j, 2i+1])
__device__ __forceinline__ void feval(const float z[HID], float dv, float dx, float k[HID],
                                      const ulonglong2* __restrict__ sW1p,
                                      const ull*        __restrict__ sb1p,
                                      const ulonglong2* __restrict__ sW2p,
                                      const ull b2p[8])
{
    ull zz[8];
    #pragma unroll
    for (int i = 0; i < 8; i++) zz[i] = splat2(z[i]);
    ull gp[8];
    #pragma unroll
    for (int i = 0; i < 8; i++) gp[i] = b2p[i];
    #pragma unroll 2
    for (int jp = 0; jp < 128; jp++) {
        ulonglong2 wa = sW1p[4 * jp + 0], wb = sW1p[4 * jp + 1];
        ulonglong2 wc = sW1p[4 * jp + 2], wd = sW1p[4 * jp + 3];
        ull hp = sb1p[jp];
        ffma2(hp, wa.x, zz[0]); ffma2(hp, wa.y, zz[1]);
        ffma2(hp, wb.x, zz[2]); ffma2(hp, wb.y, zz[3]);
        ffma2(hp, wc.x, zz[4]); ffma2(hp, wc.y, zz[5]);
        ffma2(hp, wd.x, zz[6]); ffma2(hp, wd.y, zz[7]);
        float h0, h1;
        unpack2(hp, h0, h1);
        ull hh0 = splat2(fmaxf(h0, 0.0f));
        ull hh1 = splat2(fmaxf(h1, 0.0f));
        const ulonglong2* c = sW2p + 8 * jp;     // rows j = 2jp and 2jp+1
        ulonglong2 p0 = c[0], p1 = c[1], p2 = c[2], p3 = c[3];
        ffma2(gp[0], p0.x, hh0); ffma2(gp[1], p0.y, hh0);
        ffma2(gp[2], p1.x, hh0); ffma2(gp[3], p1.y, hh0);
        ffma2(gp[4], p2.x, hh0); ffma2(gp[5], p2.y, hh0);
        ffma2(gp[6], p3.x, hh0); ffma2(gp[7], p3.y, hh0);
        ulonglong2 q0 = c[4], q1 = c[5], q2 = c[6], q3 = c[7];
        ffma2(gp[0], q0.x, hh1); ffma2(gp[1], q0.y, hh1);
        ffma2(gp[2], q1.x, hh1); ffma2(gp[3], q1.y, hh1);
        ffma2(gp[4], q2.x, hh1); ffma2(gp[5], q2.y, hh1);
        ffma2(gp[6], q3.x, hh1); ffma2(gp[7], q3.y, hh1);
    }
    #pragma unroll
    for (int i = 0; i < HID; i++) {
        float glo, ghi;
        unpack2(gp[i], glo, ghi);
        k[i] = fmaf(fast_tanh(glo), dv, fast_tanh(ghi) * dx);
    }
}

// one RK4 substep, hstep = 0.5: z += h/6 (k1 + 2k2 + 2k3 + k4)
__device__ __forceinline__ void rk_substep(float z[HID],
    float dav, float dax, float dbv, float dbx, float dcv, float dcx,
    const ulonglong2* sW1p, const ull* sb1p, const ulonglong2* sW2p, const ull b2p[8])
{
    float k[HID], zz[HID], zacc[HID];
    feval(z, dav, dax, k, sW1p, sb1p, sW2p, b2p);
    #pragma unroll
    for (int h = 0; h < HID; h++) { zacc[h] = fmaf(k[h], (1.0f/12.0f), z[h]); zz[h] = fmaf(k[h], 0.25f, z[h]); }
    feval(zz, dbv, dbx, k, sW1p, sb1p, sW2p, b2p);
    #pragma unroll
    for (int h = 0; h < HID; h++) { zacc[h] = fmaf(k[h], (1.0f/6.0f), zacc[h]); zz[h] = fmaf(k[h], 0.25f, z[h]); }
    feval(zz, dbv, dbx, k, sW1p, sb1p, sW2p, b2p);
    #pragma unroll
    for (int h = 0; h < HID; h++) { zacc[h] = fmaf(k[h], (1.0f/6.0f), zacc[h]); zz[h] = fmaf(k[h], 0.5f, z[h]); }
    feval(zz, dcv, dcx, k, sW1p, sb1p, sW2p, b2p);
    #pragma unroll
    for (int h = 0; h < HID; h++) z[h] = fmaf(k[h], (1.0f/12.0f), zacc[h]);
}

__global__ void __launch_bounds__(128, 1) ode_kernel(
    const float* __restrict__ W_init, const float* __restrict__ b_init,
    const float* __restrict__ W1, const float* __restrict__ b1,
    const float* __restrict__ W2, const float* __restrict__ b2, int B)
{
    __shared__ ulonglong2 sW1p[512];   // [jp=128][k-pairs], (W1[2jp,k], W1[2jp+1,k])
    __shared__ ull        sb1p[128];   // (b1[2jp], b1[2jp+1]) == b1 verbatim
    __shared__ ulonglong2 sW2p[1024];  // [j=256][i-pairs],  (W2[2i,j], W2[2i+1,j])
    int tid = threadIdx.x;
    float* f1 = (float*)sW1p;
    // f1[2*idx], f1[2*idx+1] = pair for ull index idx; idx = jp*8 + kk, kk = k
    for (int idx = tid; idx < 1024; idx += blockDim.x) {
        int jp = idx >> 3, kk = idx & 7;
        f1[2 * idx + 0] = W1[(2 * jp    ) * 8 + kk];
        f1[2 * idx + 1] = W1[(2 * jp + 1) * 8 + kk];
    }
    float* fb = (float*)sb1p;
    for (int idx = tid; idx < 256; idx += blockDim.x) fb[idx] = b1[idx];
    float* f2 = (float*)sW2p;
    for (int idx = tid; idx < 4096; idx += blockDim.x) {
        int j = idx >> 4, i = idx & 15;   // i indexes the 16 outputs (lane order)
        f2[idx] = W2[i * 256 + j];        // pair (2i,2i+1) contiguous -> valid f32x2
    }
    __syncthreads();

    int b = blockIdx.x * blockDim.x + tid;
    if (b >= B) return;

    ull b2p[8];
    #pragma unroll
    for (int i = 0; i < 8; i++) b2p[i] = pack2(b2[2 * i], b2[2 * i + 1]);

    float x0v = g_xv[0 * B + b], x0x = g_xv[1 * B + b];
    float m0v = g_m [0 * B + b], m0x = g_m [1 * B + b];
    float z[HID];
    #pragma unroll
    for (int h = 0; h < HID; h++)
        z[h] = fmaf(W_init[2 * h], x0v, fmaf(W_init[2 * h + 1], x0x, b_init[h]));

    for (int i = 0; i < 31; i++) {
        float x1v = g_xv[(2 * i + 2) * B + b], x1x = g_xv[(2 * i + 3) * B + b];
        float m1v = g_m [(2 * i + 2) * B + b], m1x = g_m [(2 * i + 3) * B + b];
        float ev = x0v - x1v, ex = x0x - x1x;
        // dX(s) = a(s)*(x0-x1) + b(s)*m0 + d(s)*m1
        // s=.25: (-1.125, .1875, -.3125); s=.5: (-1.5, -.25, -.25); s=.75: (-1.125, -.3125, .1875)
        float dmv = fmaf(-1.5f, ev, fmaf(-0.25f, m0v, -0.25f * m1v));   // dX(0.5)
        float dmx = fmaf(-1.5f, ex, fmaf(-0.25f, m0x, -0.25f * m1x));
        {   // substep s0 = 0: s = 0 (dX = m0), 0.25, 0.5
            float dbv = fmaf(-1.125f, ev, fmaf(0.1875f, m0v, -0.3125f * m1v));
            float dbx = fmaf(-1.125f, ex, fmaf(0.1875f, m0x, -0.3125f * m1x));
            rk_substep(z, m0v, m0x, dbv, dbx, dmv, dmx, sW1p, sb1p, sW2p, b2p);
        }
        {   // substep s0 = 0.5: s = 0.5, 0.75, 1.0 (dX = m1)
            float dbv = fmaf(-1.125f, ev, fmaf(-0.3125f, m0v, 0.1875f * m1v));
            float dbx = fmaf(-1.125f, ex, fmaf(-0.3125f, m0x, 0.1875f * m1x));
            rk_substep(z, dmv, dmx, dbv, dbx, m1v, m1x, sW1p, sb1p, sW2p, b2p);
        }
        x0v = x1v; x0x = x1x; m0v = m1v; m0x = m1x;
    }
    #pragma unroll
    for (int h = 0; h < HID; h++) g_z[h * B + b] = z[h];
}

// ---------------- kernel 3: readout MLP + epilogue ----------------
__global__ void __launch_bounds__(RB, 1) readout_kernel(
    const float* __restrict__ Wr1, const float* __restrict__ br1,
    const float* __restrict__ Wr2, const float* __restrict__ br2,
    const float* __restrict__ Wr3, const float* __restrict__ br3,
    const float* __restrict__ TR,  const float* __restrict__ Vin,
    const int*   __restrict__ fa_len,
    float* __restrict__ out, int B)
{
    extern __shared__ float sm[];
    float* sWr1  = sm;               // 1600
    float* sbr1  = sWr1 + 1600;      // 200
    float* sWr2t = sbr1 + 200;       // 40000  [j=200][i=200]
    float* sbr2  = sWr2t + 40000;    // 200
    float* sWr3  = sbr2 + 200;       // 200
    float* sh1   = sWr3 + 200;       // 200 * RB, layout [j][RB]
    int tid = threadIdx.x;
    for (int idx = tid; idx < 1600; idx += RB) sWr1[idx] = Wr1[idx];
    for (int idx = tid; idx <  200; idx += RB) { sbr1[idx] = br1[idx]; sbr2[idx] = br2[idx]; sWr3[idx] = Wr3[idx]; }
    for (int idx = tid; idx < 40000; idx += RB) {
        int j = idx / 200, i = idx % 200;
        sWr2t[idx] = Wr2[i * 200 + j];   // sWr2t[j][i] = Wr2[i][j]
    }
    __syncthreads();

    int b = blockIdx.x * RB + tid;
    if (b >= B) return;

    float z[HID];
    #pragma unroll
    for (int h = 0; h < HID; h++) z[h] = g_z[h * B + b];

    // h1 = gelu(Wr1 z + br1)
    for (int j = 0; j < 200; j++) {
        float a = sbr1[j];
        #pragma unroll
        for (int h = 0; h < HID; h++) a = fmaf(sWr1[j * 8 + h], z[h], a);
        sh1[j * RB + tid] = gelu_exact(a);
    }

    // t = Wr3 . gelu(Wr2 h1 + br2) + br3
    float t = br3[0];
    for (int i = 0; i < 200; i += 4) {
        float a0 = sbr2[i], a1 = sbr2[i + 1], a2 = sbr2[i + 2], a3 = sbr2[i + 3];
        #pragma unroll 4
        for (int j = 0; j < 200; j++) {
            float hv = sh1[j * RB + tid];
            const float4 w = *(const float4*)(sWr2t + j * 200 + i);
            a0 = fmaf(w.x, hv, a0); a1 = fmaf(w.y, hv, a1);
            a2 = fmaf(w.z, hv, a2); a3 = fmaf(w.w, hv, a3);
        }
        t = fmaf(sWr3[i    ], gelu_exact(a0), t);
        t = fmaf(sWr3[i + 1], gelu_exact(a1), t);
        t = fmaf(sWr3[i + 2], gelu_exact(a2), t);
        t = fmaf(sWr3[i + 3], gelu_exact(a3), t);
    }

    float sig = 1.0f / (1.0f + expf(-t));
    float T10 = 0.1f + sig * 6.9f;
    float E   = expf(-TR[b] / T10);

    const float* Vr = Vin + b * LSEQ;
    float xo[LSEQ];
    float s2 = 0.0f;
    #pragma unroll
    for (int j = 0; j < LSEQ; j++) {
        float v = Vr[j];
        float num = (1.0f - E) * sinf(v);
        float den = 1.0f - cosf(v) * E;
        float r = num / den;              // v==0 (padding) -> 0
        xo[j] = r; s2 += r;
    }
    float fl = (float)fa_len[b];
    float mean2 = s2 / fl;
    float inv2  = 1.0f / mean2;
    #pragma unroll
    for (int j = 0; j < LSEQ; j++) out[b * LSEQ + j] = xo[j] * inv2;
    out[B * LSEQ + b]     = T10;
    out[B * LSEQ + B + b] = 1.0f;
}

// ---------------- launcher ----------------
extern "C" void kernel_launch(void* const* d_in, const int* in_sizes, int n_in,
                              void* d_out, int out_size)
{
    const float* X_fa_in = (const float*)d_in[0];
    const float* fa_vals = (const float*)d_in[1];
    const float* TR      = (const float*)d_in[2];
    const float* W_init  = (const float*)d_in[3];
    const float* b_init  = (const float*)d_in[4];
    const float* W1      = (const float*)d_in[5];
    const float* b1      = (const float*)d_in[6];
    const float* W2      = (const float*)d_in[7];
    const float* b2      = (const float*)d_in[8];
    const float* Wr1     = (const float*)d_in[9];
    const float* br1     = (const float*)d_in[10];
    const float* Wr2     = (const float*)d_in[11];
    const float* br2     = (const float*)d_in[12];
    const float* Wr3     = (const float*)d_in[13];
    const float* br3     = (const float*)d_in[14];
    const int*   fa_len  = (const int*)d_in[16];
    int B = in_sizes[0] / LSEQ;

    setup_kernel<<<(B + 127) / 128, 128>>>(X_fa_in, fa_vals, fa_len, B);
    ode_kernel<<<(B + 127) / 128, 128>>>(W_init, b_init, W1, b1, W2, b2, B);

    const int SM_BYTES = (1600 + 200 + 40000 + 200 + 200 + 200 * RB) * 4; // 220000 B
    cudaFuncSetAttribute(readout_kernel, cudaFuncAttributeMaxDynamicSharedMemorySize, SM_BYTES);
    readout_kernel<<<(B + RB - 1) / RB, RB, SM_BYTES>>>(
        Wr1, br1, Wr2, br2, Wr3, br3, TR, fa_vals, fa_len, (float*)d_out, B);
}